// round 13
// baseline (speedup 1.0000x reference)
#include <cuda_runtime.h>
#include <cuda_bf16.h>
#include <cstdint>

// Problem constants
#define M_DIM 4096
#define K_DIM 1024
#define N_DIM 32768
#define TOPK 64
#define NCAND_TGT 96
#define CAP 128

// ---------------- device scratch (no allocs allowed) ----------------
__device__ __nv_bfloat16 g_Abf[(size_t)M_DIM * K_DIM];    // bf16(x)           8 MB
__device__ float         g_Wt[(size_t)N_DIM * K_DIM];     // fp32 W_enc^T    128 MB
__device__ __nv_bfloat16 g_Wtbf[(size_t)N_DIM * K_DIM];   // bf16 W_enc^T     64 MB
__device__ float         g_bias2[N_DIM];
__device__ __nv_bfloat16 g_actsb[(size_t)M_DIM * N_DIM];  // approx acts     256 MB
__device__ int           g_cand[M_DIM * CAP];
__device__ int           g_ncand[M_DIM];
__device__ int           g_tk_idx[M_DIM * TOPK];
__device__ float         g_tk_val[M_DIM * TOPK];

// ---------------- helpers ----------------
__device__ __forceinline__ uint32_t smem_u32(const void* p) {
    uint32_t a;
    asm("{ .reg .u64 t; cvta.to.shared.u64 t, %1; cvt.u32.u64 %0, t; }" : "=r"(a) : "l"(p));
    return a;
}
#define CP16(dst, src) \
    asm volatile("cp.async.cg.shared.global [%0], [%1], 16;" :: "r"(dst), "l"(src))
#define CP_COMMIT() asm volatile("cp.async.commit_group;")
#define LDSM4(r, addr) \
    asm volatile("ldmatrix.sync.aligned.m8n8.x4.shared.b16 {%0,%1,%2,%3}, [%4];" \
        : "=r"((r)[0]), "=r"((r)[1]), "=r"((r)[2]), "=r"((r)[3]) : "r"(addr))
#define MMA168(c, a, b0_, b1_) \
    asm volatile("mma.sync.aligned.m16n8k16.row.col.f32.bf16.bf16.f32 " \
        "{%0,%1,%2,%3}, {%4,%5,%6,%7}, {%8,%9}, {%0,%1,%2,%3};" \
        : "+f"((c)[0]), "+f"((c)[1]), "+f"((c)[2]), "+f"((c)[3]) \
        : "r"((a)[0]), "r"((a)[1]), "r"((a)[2]), "r"((a)[3]), "r"(b0_), "r"(b1_))

// ---------------- prep kernels ----------------
__global__ __launch_bounds__(256) void conv_x_kernel(const float* __restrict__ x) {
    size_t i = (size_t)blockIdx.x * 256 + threadIdx.x;
    g_Abf[i] = __float2bfloat16_rn(x[i]);
}

__global__ __launch_bounds__(1024) void transpose_w_kernel(const float* __restrict__ W) {
    __shared__ float t[32][33];
    int n0 = blockIdx.x * 32, k0 = blockIdx.y * 32;
    int tx = threadIdx.x, ty = threadIdx.y;
    t[ty][tx] = W[(size_t)(k0 + ty) * N_DIM + n0 + tx];
    __syncthreads();
    float v = t[tx][ty];                  // = W[k0+tx][n0+ty]
    size_t o = (size_t)(n0 + ty) * K_DIM + k0 + tx;
    g_Wt[o]   = v;
    g_Wtbf[o] = __float2bfloat16_rn(v);
}

__global__ __launch_bounds__(256) void bias_fold_kernel(
    const float* __restrict__ Wenc, const float* __restrict__ b_enc,
    const float* __restrict__ b_dec)
{
    int n = blockIdx.x * 256 + threadIdx.x;
    float s = 0.0f;
    #pragma unroll 4
    for (int k = 0; k < K_DIM; k++)
        s += __ldg(&b_dec[k]) * Wenc[(size_t)k * N_DIM + n];
    g_bias2[n] = b_enc[n] - s;
}

// ---------------- screening GEMM: bf16 mma.sync, 128x128x32 tiles ----------------
// g_actsb[m][n] = bf16( relu( sum_k Abf[m][k]*Wtbf[n][k] + bias2[n] ) )
// Warp-staggered phases: even warps LDSM->MMA, odd warps MMA->LDSM(next stage),
// so after each __syncthreads half the warps feed the smem crossbar while the
// other half feed the tensor pipe (breaks the CTA-wide phase lockstep that
// capped tensor util at 50%).
#define ROWB 80                       // padded row: 64B data + 16B pad (conflict-free ldmatrix)
#define ATILE_B (128 * ROWB)          // 10240
#define STG (2 * ATILE_B)             // 20480 per stage
#define NSTAGE 5
#define GEMM_SMEM (NSTAGE * STG)      // 102400

__global__ __launch_bounds__(256, 2) void gemm_screen_kernel() {
    extern __shared__ char sm[];
    const uint32_t sbase = smem_u32(sm);
    const int tid = threadIdx.x, wid = tid >> 5, lane = tid & 31;
    const int bm = blockIdx.x * 128;   // M tiles (32)
    const int bn = blockIdx.y * 128;   // N tiles (256)
    const int wr = wid & 3, wc = wid >> 2;   // warp 32(M) x 64(N)

    float acc[2][8][4];
    #pragma unroll
    for (int a = 0; a < 2; a++)
        #pragma unroll
        for (int b = 0; b < 8; b++)
            #pragma unroll
            for (int c = 0; c < 4; c++) acc[a][b][c] = 0.0f;

    // per-thread cp.async chunks: A 512 chunks, B 512 chunks; 2+2 per thread
    const int q0 = tid, q1 = tid + 256;
    const int r0 = q0 >> 2, c0 = q0 & 3;
    const int r1 = q1 >> 2, c1 = q1 & 3;

    auto ld_stage = [&](int st, int k0) {
        uint32_t ab = sbase + st * STG;
        uint32_t bb = ab + ATILE_B;
        CP16(ab + r0 * ROWB + c0 * 16, g_Abf  + (size_t)(bm + r0) * K_DIM + k0 + c0 * 8);
        CP16(ab + r1 * ROWB + c1 * 16, g_Abf  + (size_t)(bm + r1) * K_DIM + k0 + c1 * 8);
        CP16(bb + r0 * ROWB + c0 * 16, g_Wtbf + (size_t)(bn + r0) * K_DIM + k0 + c0 * 8);
        CP16(bb + r1 * ROWB + c1 * 16, g_Wtbf + (size_t)(bn + r1) * K_DIM + k0 + c1 * 8);
        CP_COMMIT();
    };

    // preload 4 stages
    ld_stage(0, 0);
    ld_stage(1, 32);
    ld_stage(2, 64);
    ld_stage(3, 96);

    const int lrow = (lane & 15) * ROWB;
    const int lcol = (lane >> 4) * 16;
    const bool odd = (wid & 1) != 0;

    // one frag set per warp (held across the barrier by odd warps)
    uint32_t a0[2][4], a1[2][4], bq[2][4][4];

    auto load_frags = [&](int buf) {
        uint32_t abase = sbase + buf * STG + (wr * 32) * ROWB + lrow + lcol;
        uint32_t bbase = sbase + buf * STG + ATILE_B + (wc * 64) * ROWB + lrow + lcol;
        #pragma unroll
        for (int ks = 0; ks < 2; ks++) {
            LDSM4(a0[ks], abase + ks * 32);
            LDSM4(a1[ks], abase + 16 * ROWB + ks * 32);
            #pragma unroll
            for (int nt = 0; nt < 4; nt++)
                LDSM4(bq[ks][nt], bbase + nt * 16 * ROWB + ks * 32);
        }
    };
    auto do_mma = [&]() {
        #pragma unroll
        for (int ks = 0; ks < 2; ks++) {
            #pragma unroll
            for (int nt = 0; nt < 4; nt++) {
                MMA168(acc[0][2 * nt],     a0[ks], bq[ks][nt][0], bq[ks][nt][2]);
                MMA168(acc[0][2 * nt + 1], a0[ks], bq[ks][nt][1], bq[ks][nt][3]);
                MMA168(acc[1][2 * nt],     a1[ks], bq[ks][nt][0], bq[ks][nt][2]);
                MMA168(acc[1][2 * nt + 1], a1[ks], bq[ks][nt][1], bq[ks][nt][3]);
            }
        }
    };

    // stage 0 resident (3 newer groups may be in flight), then odd warps preload iter-0 frags
    asm volatile("cp.async.wait_group 3;" ::: "memory");
    __syncthreads();
    if (odd) load_frags(0);

    int bcur = 0, bnext = 1, bpre = 4;   // it%5, (it+1)%5, (it+4)%5
    for (int it = 0; it < 32; it++) {
        // stages <= it+1 resident (2 newest groups may still be in flight)
        asm volatile("cp.async.wait_group 2;" ::: "memory");
        __syncthreads();
        if (it + 4 < 32) ld_stage(bpre, (it + 4) * 32);
        else             CP_COMMIT();   // keep group FIFO accounting valid at tail

        if (!odd) {
            load_frags(bcur);
            do_mma();
        } else {
            do_mma();                    // frags for stage it, loaded last iteration
            if (it + 1 < 32) load_frags(bnext);
        }

        bcur = bnext;
        if (++bnext == NSTAGE) bnext = 0;
        if (++bpre == NSTAGE) bpre = 0;
    }

    // epilogue: +bias, relu, bf16 store
    #pragma unroll
    for (int mt = 0; mt < 2; mt++) {
        int row0 = bm + wr * 32 + mt * 16 + (lane >> 2);
        #pragma unroll
        for (int nt = 0; nt < 8; nt++) {
            int col = bn + wc * 64 + nt * 8 + (lane & 3) * 2;
            float2 bb = *reinterpret_cast<const float2*>(&g_bias2[col]);
            float v0 = fmaxf(acc[mt][nt][0] + bb.x, 0.0f);
            float v1 = fmaxf(acc[mt][nt][1] + bb.y, 0.0f);
            float v2 = fmaxf(acc[mt][nt][2] + bb.x, 0.0f);
            float v3 = fmaxf(acc[mt][nt][3] + bb.y, 0.0f);
            __nv_bfloat162 p0 = __floats2bfloat162_rn(v0, v1);
            __nv_bfloat162 p1 = __floats2bfloat162_rn(v2, v3);
            *reinterpret_cast<__nv_bfloat162*>(&g_actsb[(size_t)row0 * N_DIM + col]) = p0;
            *reinterpret_cast<__nv_bfloat162*>(&g_actsb[(size_t)(row0 + 8) * N_DIM + col]) = p1;
        }
    }
}

// ---------------- screening top-96 candidates (2-round radix on bf16 bits) ----------------
#define SCREEN_SMEM (65536 + 1024 + 64)
__global__ __launch_bounds__(256) void screen_kernel() {
    extern __shared__ char sm[];
    uint16_t* row = reinterpret_cast<uint16_t*>(sm);           // 65536 B
    unsigned* hist = reinterpret_cast<unsigned*>(sm + 65536);  // 256 * 4
    __shared__ int s_b, s_krem, s_T, s_cnt;
    const int r = blockIdx.x, tid = threadIdx.x;

    const uint4* src = reinterpret_cast<const uint4*>(g_actsb + (size_t)r * N_DIM);
    uint4* drow = reinterpret_cast<uint4*>(row);
    for (int i = tid; i < N_DIM / 8; i += 256) drow[i] = src[i];
    hist[tid] = 0u;
    __syncthreads();

    // round 1: high byte (positive bf16 bits order like values)
    const uint32_t* row32 = reinterpret_cast<const uint32_t*>(row);
    for (int i = tid; i < N_DIM / 2; i += 256) {
        uint32_t w = row32[i];
        uint32_t lo = w & 0xFFFFu, hi = w >> 16;
        if (lo) atomicAdd(&hist[lo >> 8], 1u);
        if (hi) atomicAdd(&hist[hi >> 8], 1u);
    }
    __syncthreads();
    if (tid == 0) {
        unsigned cum = 0; int b = 255;
        for (; b > 0; b--) {
            unsigned c = hist[b];
            if (cum + c >= (unsigned)NCAND_TGT) break;
            cum += c;
        }
        s_b = b; s_krem = NCAND_TGT - (int)cum;
    }
    __syncthreads();
    const int b = s_b;
    hist[tid] = 0u;
    __syncthreads();

    // round 2: low byte within bin b
    for (int i = tid; i < N_DIM; i += 256) {
        unsigned u = row[i];
        if ((int)(u >> 8) == b) atomicAdd(&hist[u & 0xFFu], 1u);
    }
    __syncthreads();
    if (tid == 0) {
        int krem = s_krem;
        unsigned cum = 0; int s2 = 255;
        for (; s2 > 0; s2--) {
            unsigned c = hist[s2];
            if (cum + c >= (unsigned)krem) break;
            cum += c;
        }
        s_T = (b << 8) | s2;
        s_cnt = 0;
    }
    __syncthreads();
    const unsigned T = (unsigned)s_T;

    // compact: strictly greater first (guaranteed < NCAND_TGT), then equals up to CAP
    for (int i = tid; i < N_DIM; i += 256) {
        unsigned u = row[i];
        if (u > T) {
            int p = atomicAdd(&s_cnt, 1);
            if (p < CAP) g_cand[r * CAP + p] = i;
        }
    }
    __syncthreads();
    for (int i = tid; i < N_DIM; i += 256) {
        unsigned u = row[i];
        if (u == T && u) {
            int p = atomicAdd(&s_cnt, 1);
            if (p < CAP) g_cand[r * CAP + p] = i;
        }
    }
    __syncthreads();
    if (tid == 0) g_ncand[r] = s_cnt < CAP ? s_cnt : CAP;
}

// ---------------- exact rescore + final top-64 ----------------
__global__ __launch_bounds__(256) void rescore_kernel(const float* __restrict__ x) {
    __shared__ float sx[K_DIM];
    __shared__ unsigned long long skey[CAP];
    const int r = blockIdx.x, tid = threadIdx.x;
    const int wid = tid >> 5, lane = tid & 31;

    for (int i = tid; i < K_DIM / 4; i += 256)
        *reinterpret_cast<float4*>(&sx[i * 4]) =
            *reinterpret_cast<const float4*>(&x[(size_t)r * K_DIM + i * 4]);
    if (tid < CAP) skey[tid] = 0ull;
    __syncthreads();

    const int nc = g_ncand[r];
    for (int j = wid; j < nc; j += 8) {
        const int cand = g_cand[r * CAP + j];
        const float4* wrow = reinterpret_cast<const float4*>(&g_Wt[(size_t)cand * K_DIM]);
        const float4* xr = reinterpret_cast<const float4*>(sx);
        float s = 0.0f;
        #pragma unroll
        for (int c = lane; c < 256; c += 32) {
            float4 w = wrow[c];
            float4 v = xr[c];
            s = fmaf(w.x, v.x, s); s = fmaf(w.y, v.y, s);
            s = fmaf(w.z, v.z, s); s = fmaf(w.w, v.w, s);
        }
        #pragma unroll
        for (int o = 16; o > 0; o >>= 1) s += __shfl_xor_sync(0xFFFFFFFFu, s, o);
        if (lane == 0) {
            float v = fmaxf(s + g_bias2[cand], 0.0f);
            skey[j] = ((unsigned long long)__float_as_uint(v) << 32) |
                      (unsigned long long)(~(unsigned)cand);
        }
    }
    __syncthreads();

    // bitonic sort CAP=128 keys ascending
    for (int ksz = 2; ksz <= CAP; ksz <<= 1) {
        for (int j = ksz >> 1; j > 0; j >>= 1) {
            if (tid < CAP) {
                int ixj = tid ^ j;
                if (ixj > tid) {
                    bool up = ((tid & ksz) == 0);
                    unsigned long long A = skey[tid], B = skey[ixj];
                    if (up ? (A > B) : (A < B)) { skey[tid] = B; skey[ixj] = A; }
                }
            }
            __syncthreads();
        }
    }

    if (tid < TOPK) {
        unsigned long long k = skey[CAP - 1 - tid];   // largest first
        g_tk_val[r * TOPK + tid] = __uint_as_float((unsigned)(k >> 32));
        g_tk_idx[r * TOPK + tid] = (int)(~(unsigned)(k & 0xFFFFFFFFull));
    }
}

// ---------------- sparse matryoshka decode ----------------
__global__ __launch_bounds__(256) void decode_kernel(
    const float* __restrict__ Wdec, const float* __restrict__ b_dec,
    float* __restrict__ out)
{
    const int row = blockIdx.x;
    const int tid = threadIdx.x;

    __shared__ int   sIdx[TOPK];
    __shared__ float sVal[TOPK];
    if (tid < TOPK) {
        sIdx[tid] = g_tk_idx[row * TOPK + tid];
        sVal[tid] = g_tk_val[row * TOPK + tid];
    }
    __syncthreads();

    const int d = tid * 4;
    float4 bd = *reinterpret_cast<const float4*>(&b_dec[d]);
    float4 s1 = make_float4(0.f, 0.f, 0.f, 0.f);
    float4 s2 = s1, s3 = s1;

    #pragma unroll 8
    for (int j = 0; j < TOPK; j++) {
        int   id = sIdx[j];
        float v  = sVal[j];
        float4 w = *reinterpret_cast<const float4*>(&Wdec[(size_t)id * K_DIM + d]);
        s3.x = fmaf(v, w.x, s3.x); s3.y = fmaf(v, w.y, s3.y);
        s3.z = fmaf(v, w.z, s3.z); s3.w = fmaf(v, w.w, s3.w);
        if (id < 8192) {
            s2.x = fmaf(v, w.x, s2.x); s2.y = fmaf(v, w.y, s2.y);
            s2.z = fmaf(v, w.z, s2.z); s2.w = fmaf(v, w.w, s2.w);
        }
        if (id < 2048) {
            s1.x = fmaf(v, w.x, s1.x); s1.y = fmaf(v, w.y, s1.y);
            s1.z = fmaf(v, w.z, s1.z); s1.w = fmaf(v, w.w, s1.w);
        }
    }

    const size_t roff = (size_t)row * K_DIM + d;
    const size_t gstride = (size_t)M_DIM * K_DIM;
    *reinterpret_cast<float4*>(&out[roff]) =
        make_float4(bd.x + s1.x, bd.y + s1.y, bd.z + s1.z, bd.w + s1.w);
    *reinterpret_cast<float4*>(&out[gstride + roff]) =
        make_float4(bd.x + s2.x, bd.y + s2.y, bd.z + s2.z, bd.w + s2.w);
    *reinterpret_cast<float4*>(&out[2 * gstride + roff]) =
        make_float4(bd.x + s3.x, bd.y + s3.y, bd.z + s3.z, bd.w + s3.w);
}

// ---------------- launch ----------------
extern "C" void kernel_launch(void* const* d_in, const int* in_sizes, int n_in,
                              void* d_out, int out_size)
{
    const float* x     = (const float*)d_in[0];  // [4096,1024]
    const float* W_enc = (const float*)d_in[1];  // [1024,32768]
    const float* b_enc = (const float*)d_in[2];  // [32768]
    const float* W_dec = (const float*)d_in[3];  // [32768,1024]
    const float* b_dec = (const float*)d_in[4];  // [1024]
    float* out = (float*)d_out;                  // [3,4096,1024]

    cudaFuncSetAttribute(gemm_screen_kernel,
                         cudaFuncAttributeMaxDynamicSharedMemorySize, GEMM_SMEM);
    cudaFuncSetAttribute(screen_kernel,
                         cudaFuncAttributeMaxDynamicSharedMemorySize, SCREEN_SMEM);

    conv_x_kernel<<<(M_DIM * K_DIM) / 256, 256>>>(x);
    transpose_w_kernel<<<dim3(N_DIM / 32, K_DIM / 32), dim3(32, 32)>>>(W_enc);
    bias_fold_kernel<<<N_DIM / 256, 256>>>(W_enc, b_enc, b_dec);

    gemm_screen_kernel<<<dim3(M_DIM / 128, N_DIM / 128), 256, GEMM_SMEM>>>();

    screen_kernel<<<M_DIM, 256, SCREEN_SMEM>>>();
    rescore_kernel<<<M_DIM, 256>>>(x);
    decode_kernel<<<M_DIM, 256>>>(W_dec, b_dec, out);
}

// round 14
// speedup vs baseline: 1.0917x; 1.0917x over previous
#include <cuda_runtime.h>
#include <cuda_bf16.h>
#include <cstdint>

// Problem constants
#define M_DIM 4096
#define K_DIM 1024
#define N_DIM 32768
#define TOPK 64
#define NCAND_TGT 96
#define CAP 128

// ---------------- device scratch (no allocs allowed) ----------------
__device__ __nv_bfloat16 g_Abf[(size_t)M_DIM * K_DIM];    // bf16(x)           8 MB
__device__ float         g_Wt[(size_t)N_DIM * K_DIM];     // fp32 W_enc^T    128 MB
__device__ __nv_bfloat16 g_Wtbf[(size_t)N_DIM * K_DIM];   // bf16 W_enc^T     64 MB
__device__ float         g_bias2[N_DIM];
__device__ __nv_bfloat16 g_actsb[(size_t)M_DIM * N_DIM];  // approx acts     256 MB
__device__ int           g_cand[M_DIM * CAP];
__device__ int           g_ncand[M_DIM];
__device__ int           g_tk_idx[M_DIM * TOPK];
__device__ float         g_tk_val[M_DIM * TOPK];

// ---------------- helpers ----------------
__device__ __forceinline__ uint32_t smem_u32(const void* p) {
    uint32_t a;
    asm("{ .reg .u64 t; cvta.to.shared.u64 t, %1; cvt.u32.u64 %0, t; }" : "=r"(a) : "l"(p));
    return a;
}
#define CP16(dst, src) \
    asm volatile("cp.async.cg.shared.global [%0], [%1], 16;" :: "r"(dst), "l"(src))
#define CP_COMMIT() asm volatile("cp.async.commit_group;")
#define LDSM4(r, addr) \
    asm volatile("ldmatrix.sync.aligned.m8n8.x4.shared.b16 {%0,%1,%2,%3}, [%4];" \
        : "=r"((r)[0]), "=r"((r)[1]), "=r"((r)[2]), "=r"((r)[3]) : "r"(addr))
#define MMA168(c, a, b0_, b1_) \
    asm volatile("mma.sync.aligned.m16n8k16.row.col.f32.bf16.bf16.f32 " \
        "{%0,%1,%2,%3}, {%4,%5,%6,%7}, {%8,%9}, {%0,%1,%2,%3};" \
        : "+f"((c)[0]), "+f"((c)[1]), "+f"((c)[2]), "+f"((c)[3]) \
        : "r"((a)[0]), "r"((a)[1]), "r"((a)[2]), "r"((a)[3]), "r"(b0_), "r"(b1_))

// ---------------- prep kernels ----------------
__global__ __launch_bounds__(256) void conv_x_kernel(const float* __restrict__ x) {
    size_t i = (size_t)blockIdx.x * 256 + threadIdx.x;
    g_Abf[i] = __float2bfloat16_rn(x[i]);
}

__global__ __launch_bounds__(1024) void transpose_w_kernel(const float* __restrict__ W) {
    __shared__ float t[32][33];
    int n0 = blockIdx.x * 32, k0 = blockIdx.y * 32;
    int tx = threadIdx.x, ty = threadIdx.y;
    t[ty][tx] = W[(size_t)(k0 + ty) * N_DIM + n0 + tx];
    __syncthreads();
    float v = t[tx][ty];                  // = W[k0+tx][n0+ty]
    size_t o = (size_t)(n0 + ty) * K_DIM + k0 + tx;
    g_Wt[o]   = v;
    g_Wtbf[o] = __float2bfloat16_rn(v);
}

__global__ __launch_bounds__(256) void bias_fold_kernel(
    const float* __restrict__ Wenc, const float* __restrict__ b_enc,
    const float* __restrict__ b_dec)
{
    int n = blockIdx.x * 256 + threadIdx.x;
    float s = 0.0f;
    #pragma unroll 4
    for (int k = 0; k < K_DIM; k++)
        s += __ldg(&b_dec[k]) * Wenc[(size_t)k * N_DIM + n];
    g_bias2[n] = b_enc[n] - s;
}

// ---------------- screening GEMM: bf16 mma.sync, 128x128x32 tiles ----------------
// g_actsb[m][n] = bf16( relu( sum_k Abf[m][k]*Wtbf[n][k] + bias2[n] ) )
// ks-granularity parity stagger with a SINGLE frag array (24 regs):
//   even warps: LDSM ks0 -> MMA ks0 -> LDSM ks1 -> MMA ks1
//   odd  warps: MMA ks0 (loaded at end of previous iter) -> LDSM ks1 -> MMA ks1
//               -> LDSM ks0(next stage)
// After each __syncthreads, odd warps feed the tensor pipe while even warps use
// the smem crossbar, swapping mid-iteration -> overlapped phases without the
// register blow-up that sank the full-stage-stagger attempt (R13: 128 regs+spills).
#define ROWB 80                       // padded row: 64B data + 16B pad (conflict-free ldmatrix)
#define ATILE_B (128 * ROWB)          // 10240
#define STG (2 * ATILE_B)             // 20480 per stage
#define NSTAGE 5
#define GEMM_SMEM (NSTAGE * STG)      // 102400

__global__ __launch_bounds__(256, 2) void gemm_screen_kernel() {
    extern __shared__ char sm[];
    const uint32_t sbase = smem_u32(sm);
    const int tid = threadIdx.x, wid = tid >> 5, lane = tid & 31;
    const int bm = blockIdx.x * 128;   // M tiles (32)
    const int bn = blockIdx.y * 128;   // N tiles (256)
    const int wr = wid & 3, wc = wid >> 2;   // warp 32(M) x 64(N)

    float acc[2][8][4];
    #pragma unroll
    for (int a = 0; a < 2; a++)
        #pragma unroll
        for (int b = 0; b < 8; b++)
            #pragma unroll
            for (int c = 0; c < 4; c++) acc[a][b][c] = 0.0f;

    // per-thread cp.async chunks: A 512 chunks, B 512 chunks; 2+2 per thread
    const int q0 = tid, q1 = tid + 256;
    const int r0 = q0 >> 2, c0 = q0 & 3;
    const int r1 = q1 >> 2, c1 = q1 & 3;

    auto ld_stage = [&](int st, int k0) {
        uint32_t ab = sbase + st * STG;
        uint32_t bb = ab + ATILE_B;
        CP16(ab + r0 * ROWB + c0 * 16, g_Abf  + (size_t)(bm + r0) * K_DIM + k0 + c0 * 8);
        CP16(ab + r1 * ROWB + c1 * 16, g_Abf  + (size_t)(bm + r1) * K_DIM + k0 + c1 * 8);
        CP16(bb + r0 * ROWB + c0 * 16, g_Wtbf + (size_t)(bn + r0) * K_DIM + k0 + c0 * 8);
        CP16(bb + r1 * ROWB + c1 * 16, g_Wtbf + (size_t)(bn + r1) * K_DIM + k0 + c1 * 8);
        CP_COMMIT();
    };

    // preload 4 stages
    ld_stage(0, 0);
    ld_stage(1, 32);
    ld_stage(2, 64);
    ld_stage(3, 96);

    const int lrow = (lane & 15) * ROWB;
    const int lcol = (lane >> 4) * 16;
    const bool odd = (wid & 1) != 0;
    const uint32_t aoff = (wr * 32) * ROWB + lrow + lcol;
    const uint32_t boff = ATILE_B + (wc * 64) * ROWB + lrow + lcol;

    // ONE frag set (24 regs), shared by both parities / both k-steps
    uint32_t a0[4], a1[4], bq[4][4];

    auto load_ks = [&](int buf, int ks) {
        uint32_t abase = sbase + buf * STG + aoff + ks * 32;
        uint32_t bbase = sbase + buf * STG + boff + ks * 32;
        LDSM4(a0, abase);
        LDSM4(a1, abase + 16 * ROWB);
        #pragma unroll
        for (int nt = 0; nt < 4; nt++)
            LDSM4(bq[nt], bbase + nt * 16 * ROWB);
    };
    auto mma_ks = [&]() {
        #pragma unroll
        for (int nt = 0; nt < 4; nt++) {
            MMA168(acc[0][2 * nt],     a0, bq[nt][0], bq[nt][2]);
            MMA168(acc[0][2 * nt + 1], a0, bq[nt][1], bq[nt][3]);
            MMA168(acc[1][2 * nt],     a1, bq[nt][0], bq[nt][2]);
            MMA168(acc[1][2 * nt + 1], a1, bq[nt][1], bq[nt][3]);
        }
    };

    // stage 0 resident, then odd warps preload iter-0 ks0 frags
    asm volatile("cp.async.wait_group 3;" ::: "memory");
    __syncthreads();
    if (odd) load_ks(0, 0);

    int bcur = 0, bnext = 1, bpre = 4;   // it%5, (it+1)%5, (it+4)%5
    for (int it = 0; it < 32; it++) {
        // stages <= it+1 resident (2 newest commits may still be in flight)
        asm volatile("cp.async.wait_group 2;" ::: "memory");
        __syncthreads();
        if (it + 4 < 32) ld_stage(bpre, (it + 4) * 32);
        else             CP_COMMIT();   // keep group FIFO accounting valid at tail

        if (!odd) {
            load_ks(bcur, 0);
            mma_ks();
            load_ks(bcur, 1);
            mma_ks();
        } else {
            mma_ks();                    // ks0 of stage it, loaded last iteration
            load_ks(bcur, 1);
            mma_ks();
            if (it + 1 < 32) load_ks(bnext, 0);
        }

        bcur = bnext;
        if (++bnext == NSTAGE) bnext = 0;
        if (++bpre == NSTAGE) bpre = 0;
    }

    // epilogue: +bias, relu, bf16 store
    #pragma unroll
    for (int mt = 0; mt < 2; mt++) {
        int row0 = bm + wr * 32 + mt * 16 + (lane >> 2);
        #pragma unroll
        for (int nt = 0; nt < 8; nt++) {
            int col = bn + wc * 64 + nt * 8 + (lane & 3) * 2;
            float2 bb = *reinterpret_cast<const float2*>(&g_bias2[col]);
            float v0 = fmaxf(acc[mt][nt][0] + bb.x, 0.0f);
            float v1 = fmaxf(acc[mt][nt][1] + bb.y, 0.0f);
            float v2 = fmaxf(acc[mt][nt][2] + bb.x, 0.0f);
            float v3 = fmaxf(acc[mt][nt][3] + bb.y, 0.0f);
            __nv_bfloat162 p0 = __floats2bfloat162_rn(v0, v1);
            __nv_bfloat162 p1 = __floats2bfloat162_rn(v2, v3);
            *reinterpret_cast<__nv_bfloat162*>(&g_actsb[(size_t)row0 * N_DIM + col]) = p0;
            *reinterpret_cast<__nv_bfloat162*>(&g_actsb[(size_t)(row0 + 8) * N_DIM + col]) = p1;
        }
    }
}

// ---------------- screening top-96 candidates (2-round radix on bf16 bits) ----------------
#define SCREEN_SMEM (65536 + 1024 + 64)
__global__ __launch_bounds__(256) void screen_kernel() {
    extern __shared__ char sm[];
    uint16_t* row = reinterpret_cast<uint16_t*>(sm);           // 65536 B
    unsigned* hist = reinterpret_cast<unsigned*>(sm + 65536);  // 256 * 4
    __shared__ int s_b, s_krem, s_T, s_cnt;
    const int r = blockIdx.x, tid = threadIdx.x;

    const uint4* src = reinterpret_cast<const uint4*>(g_actsb + (size_t)r * N_DIM);
    uint4* drow = reinterpret_cast<uint4*>(row);
    for (int i = tid; i < N_DIM / 8; i += 256) drow[i] = src[i];
    hist[tid] = 0u;
    __syncthreads();

    // round 1: high byte (positive bf16 bits order like values)
    const uint32_t* row32 = reinterpret_cast<const uint32_t*>(row);
    for (int i = tid; i < N_DIM / 2; i += 256) {
        uint32_t w = row32[i];
        uint32_t lo = w & 0xFFFFu, hi = w >> 16;
        if (lo) atomicAdd(&hist[lo >> 8], 1u);
        if (hi) atomicAdd(&hist[hi >> 8], 1u);
    }
    __syncthreads();
    if (tid == 0) {
        unsigned cum = 0; int b = 255;
        for (; b > 0; b--) {
            unsigned c = hist[b];
            if (cum + c >= (unsigned)NCAND_TGT) break;
            cum += c;
        }
        s_b = b; s_krem = NCAND_TGT - (int)cum;
    }
    __syncthreads();
    const int b = s_b;
    hist[tid] = 0u;
    __syncthreads();

    // round 2: low byte within bin b
    for (int i = tid; i < N_DIM; i += 256) {
        unsigned u = row[i];
        if ((int)(u >> 8) == b) atomicAdd(&hist[u & 0xFFu], 1u);
    }
    __syncthreads();
    if (tid == 0) {
        int krem = s_krem;
        unsigned cum = 0; int s2 = 255;
        for (; s2 > 0; s2--) {
            unsigned c = hist[s2];
            if (cum + c >= (unsigned)krem) break;
            cum += c;
        }
        s_T = (b << 8) | s2;
        s_cnt = 0;
    }
    __syncthreads();
    const unsigned T = (unsigned)s_T;

    // compact: strictly greater first (guaranteed < NCAND_TGT), then equals up to CAP
    for (int i = tid; i < N_DIM; i += 256) {
        unsigned u = row[i];
        if (u > T) {
            int p = atomicAdd(&s_cnt, 1);
            if (p < CAP) g_cand[r * CAP + p] = i;
        }
    }
    __syncthreads();
    for (int i = tid; i < N_DIM; i += 256) {
        unsigned u = row[i];
        if (u == T && u) {
            int p = atomicAdd(&s_cnt, 1);
            if (p < CAP) g_cand[r * CAP + p] = i;
        }
    }
    __syncthreads();
    if (tid == 0) g_ncand[r] = s_cnt < CAP ? s_cnt : CAP;
}

// ---------------- exact rescore + final top-64 ----------------
__global__ __launch_bounds__(256) void rescore_kernel(const float* __restrict__ x) {
    __shared__ float sx[K_DIM];
    __shared__ unsigned long long skey[CAP];
    const int r = blockIdx.x, tid = threadIdx.x;
    const int wid = tid >> 5, lane = tid & 31;

    for (int i = tid; i < K_DIM / 4; i += 256)
        *reinterpret_cast<float4*>(&sx[i * 4]) =
            *reinterpret_cast<const float4*>(&x[(size_t)r * K_DIM + i * 4]);
    if (tid < CAP) skey[tid] = 0ull;
    __syncthreads();

    const int nc = g_ncand[r];
    for (int j = wid; j < nc; j += 8) {
        const int cand = g_cand[r * CAP + j];
        const float4* wrow = reinterpret_cast<const float4*>(&g_Wt[(size_t)cand * K_DIM]);
        const float4* xr = reinterpret_cast<const float4*>(sx);
        float s = 0.0f;
        #pragma unroll
        for (int c = lane; c < 256; c += 32) {
            float4 w = wrow[c];
            float4 v = xr[c];
            s = fmaf(w.x, v.x, s); s = fmaf(w.y, v.y, s);
            s = fmaf(w.z, v.z, s); s = fmaf(w.w, v.w, s);
        }
        #pragma unroll
        for (int o = 16; o > 0; o >>= 1) s += __shfl_xor_sync(0xFFFFFFFFu, s, o);
        if (lane == 0) {
            float v = fmaxf(s + g_bias2[cand], 0.0f);
            skey[j] = ((unsigned long long)__float_as_uint(v) << 32) |
                      (unsigned long long)(~(unsigned)cand);
        }
    }
    __syncthreads();

    // bitonic sort CAP=128 keys ascending
    for (int ksz = 2; ksz <= CAP; ksz <<= 1) {
        for (int j = ksz >> 1; j > 0; j >>= 1) {
            if (tid < CAP) {
                int ixj = tid ^ j;
                if (ixj > tid) {
                    bool up = ((tid & ksz) == 0);
                    unsigned long long A = skey[tid], B = skey[ixj];
                    if (up ? (A > B) : (A < B)) { skey[tid] = B; skey[ixj] = A; }
                }
            }
            __syncthreads();
        }
    }

    if (tid < TOPK) {
        unsigned long long k = skey[CAP - 1 - tid];   // largest first
        g_tk_val[r * TOPK + tid] = __uint_as_float((unsigned)(k >> 32));
        g_tk_idx[r * TOPK + tid] = (int)(~(unsigned)(k & 0xFFFFFFFFull));
    }
}

// ---------------- sparse matryoshka decode ----------------
__global__ __launch_bounds__(256) void decode_kernel(
    const float* __restrict__ Wdec, const float* __restrict__ b_dec,
    float* __restrict__ out)
{
    const int row = blockIdx.x;
    const int tid = threadIdx.x;

    __shared__ int   sIdx[TOPK];
    __shared__ float sVal[TOPK];
    if (tid < TOPK) {
        sIdx[tid] = g_tk_idx[row * TOPK + tid];
        sVal[tid] = g_tk_val[row * TOPK + tid];
    }
    __syncthreads();

    const int d = tid * 4;
    float4 bd = *reinterpret_cast<const float4*>(&b_dec[d]);
    float4 s1 = make_float4(0.f, 0.f, 0.f, 0.f);
    float4 s2 = s1, s3 = s1;

    #pragma unroll 8
    for (int j = 0; j < TOPK; j++) {
        int   id = sIdx[j];
        float v  = sVal[j];
        float4 w = *reinterpret_cast<const float4*>(&Wdec[(size_t)id * K_DIM + d]);
        s3.x = fmaf(v, w.x, s3.x); s3.y = fmaf(v, w.y, s3.y);
        s3.z = fmaf(v, w.z, s3.z); s3.w = fmaf(v, w.w, s3.w);
        if (id < 8192) {
            s2.x = fmaf(v, w.x, s2.x); s2.y = fmaf(v, w.y, s2.y);
            s2.z = fmaf(v, w.z, s2.z); s2.w = fmaf(v, w.w, s2.w);
        }
        if (id < 2048) {
            s1.x = fmaf(v, w.x, s1.x); s1.y = fmaf(v, w.y, s1.y);
            s1.z = fmaf(v, w.z, s1.z); s1.w = fmaf(v, w.w, s1.w);
        }
    }

    const size_t roff = (size_t)row * K_DIM + d;
    const size_t gstride = (size_t)M_DIM * K_DIM;
    *reinterpret_cast<float4*>(&out[roff]) =
        make_float4(bd.x + s1.x, bd.y + s1.y, bd.z + s1.z, bd.w + s1.w);
    *reinterpret_cast<float4*>(&out[gstride + roff]) =
        make_float4(bd.x + s2.x, bd.y + s2.y, bd.z + s2.z, bd.w + s2.w);
    *reinterpret_cast<float4*>(&out[2 * gstride + roff]) =
        make_float4(bd.x + s3.x, bd.y + s3.y, bd.z + s3.z, bd.w + s3.w);
}

// ---------------- launch ----------------
extern "C" void kernel_launch(void* const* d_in, const int* in_sizes, int n_in,
                              void* d_out, int out_size)
{
    const float* x     = (const float*)d_in[0];  // [4096,1024]
    const float* W_enc = (const float*)d_in[1];  // [1024,32768]
    const float* b_enc = (const float*)d_in[2];  // [32768]
    const float* W_dec = (const float*)d_in[3];  // [32768,1024]
    const float* b_dec = (const float*)d_in[4];  // [1024]
    float* out = (float*)d_out;                  // [3,4096,1024]

    cudaFuncSetAttribute(gemm_screen_kernel,
                         cudaFuncAttributeMaxDynamicSharedMemorySize, GEMM_SMEM);
    cudaFuncSetAttribute(screen_kernel,
                         cudaFuncAttributeMaxDynamicSharedMemorySize, SCREEN_SMEM);

    conv_x_kernel<<<(M_DIM * K_DIM) / 256, 256>>>(x);
    transpose_w_kernel<<<dim3(N_DIM / 32, K_DIM / 32), dim3(32, 32)>>>(W_enc);
    bias_fold_kernel<<<N_DIM / 256, 256>>>(W_enc, b_enc, b_dec);

    gemm_screen_kernel<<<dim3(M_DIM / 128, N_DIM / 128), 256, GEMM_SMEM>>>();

    screen_kernel<<<M_DIM, 256, SCREEN_SMEM>>>();
    rescore_kernel<<<M_DIM, 256>>>(x);
    decode_kernel<<<M_DIM, 256>>>(W_dec, b_dec, out);
}

// round 17
// speedup vs baseline: 1.0962x; 1.0042x over previous
#include <cuda_runtime.h>
#include <cuda_bf16.h>
#include <cstdint>

// Problem constants
#define M_DIM 4096
#define K_DIM 1024
#define N_DIM 32768
#define TOPK 64
#define NCAND_TGT 96
#define CAP 128

// ---------------- device scratch (no allocs allowed) ----------------
__device__ __nv_bfloat16 g_Abf[(size_t)M_DIM * K_DIM];    // bf16(x)           8 MB
__device__ float         g_Wt[(size_t)N_DIM * K_DIM];     // fp32 W_enc^T    128 MB
__device__ __nv_bfloat16 g_Wtbf[(size_t)N_DIM * K_DIM];   // bf16 W_enc^T     64 MB
__device__ float         g_bias2[N_DIM];
__device__ __nv_bfloat16 g_actsb[(size_t)M_DIM * N_DIM];  // approx acts     256 MB
__device__ int           g_cand[M_DIM * CAP];
__device__ int           g_ncand[M_DIM];
__device__ int           g_tk_idx[M_DIM * TOPK];
__device__ float         g_tk_val[M_DIM * TOPK];

// ---------------- helpers ----------------
__device__ __forceinline__ uint32_t smem_u32(const void* p) {
    uint32_t a;
    asm("{ .reg .u64 t; cvta.to.shared.u64 t, %1; cvt.u32.u64 %0, t; }" : "=r"(a) : "l"(p));
    return a;
}
#define CP16(dst, src) \
    asm volatile("cp.async.cg.shared.global [%0], [%1], 16;" :: "r"(dst), "l"(src))
#define CP_COMMIT() asm volatile("cp.async.commit_group;")
#define LDSM4(r, addr) \
    asm volatile("ldmatrix.sync.aligned.m8n8.x4.shared.b16 {%0,%1,%2,%3}, [%4];" \
        : "=r"((r)[0]), "=r"((r)[1]), "=r"((r)[2]), "=r"((r)[3]) : "r"(addr))
#define MMA168(c, a, b0_, b1_) \
    asm volatile("mma.sync.aligned.m16n8k16.row.col.f32.bf16.bf16.f32 " \
        "{%0,%1,%2,%3}, {%4,%5,%6,%7}, {%8,%9}, {%0,%1,%2,%3};" \
        : "+f"((c)[0]), "+f"((c)[1]), "+f"((c)[2]), "+f"((c)[3]) \
        : "r"((a)[0]), "r"((a)[1]), "r"((a)[2]), "r"((a)[3]), "r"(b0_), "r"(b1_))

// ---------------- prep kernels ----------------
__global__ __launch_bounds__(256) void conv_x_kernel(const float* __restrict__ x) {
    size_t i = (size_t)blockIdx.x * 256 + threadIdx.x;
    g_Abf[i] = __float2bfloat16_rn(x[i]);
}

__global__ __launch_bounds__(1024) void transpose_w_kernel(const float* __restrict__ W) {
    __shared__ float t[32][33];
    int n0 = blockIdx.x * 32, k0 = blockIdx.y * 32;
    int tx = threadIdx.x, ty = threadIdx.y;
    t[ty][tx] = W[(size_t)(k0 + ty) * N_DIM + n0 + tx];
    __syncthreads();
    float v = t[tx][ty];                  // = W[k0+tx][n0+ty]
    size_t o = (size_t)(n0 + ty) * K_DIM + k0 + tx;
    g_Wt[o]   = v;
    g_Wtbf[o] = __float2bfloat16_rn(v);
}

__global__ __launch_bounds__(256) void bias_fold_kernel(
    const float* __restrict__ Wenc, const float* __restrict__ b_enc,
    const float* __restrict__ b_dec)
{
    int n = blockIdx.x * 256 + threadIdx.x;
    float s = 0.0f;
    #pragma unroll 4
    for (int k = 0; k < K_DIM; k++)
        s += __ldg(&b_dec[k]) * Wenc[(size_t)k * N_DIM + n];
    g_bias2[n] = b_enc[n] - s;
}

// ---------------- screening GEMM: bf16 mma.sync, 128x128x32 tiles ----------------
// g_actsb[m][n] = bf16( relu( sum_k Abf[m][k]*Wtbf[n][k] + bias2[n] ) )
// ks-granularity parity stagger. CRITICAL: parity = (wid>>2)&1, NOT wid&1.
// SMSP assignment is wid%4, so wid&1 put identical parity in each SMSP (warps
// {0,4} both even, {1,5} both odd...) -> zero overlap within the unit that owns
// the tensor pipe + LSU port (the R13/R14 failure). (wid>>2)&1 puts one even +
// one odd warp per SMSP per CTA, so each SMSP always has a warp feeding its
// tensor pipe while another drives the smem crossbar.
#define ROWB 80                       // padded row: 64B data + 16B pad (conflict-free ldmatrix)
#define ATILE_B (128 * ROWB)          // 10240
#define STG (2 * ATILE_B)             // 20480 per stage
#define NSTAGE 5
#define GEMM_SMEM (NSTAGE * STG)      // 102400

__global__ __launch_bounds__(256, 2) void gemm_screen_kernel() {
    extern __shared__ char sm[];
    const uint32_t sbase = smem_u32(sm);
    const int tid = threadIdx.x, wid = tid >> 5, lane = tid & 31;
    const int bm = blockIdx.x * 128;   // M tiles (32)
    const int bn = blockIdx.y * 128;   // N tiles (256)
    const int wr = wid & 3, wc = wid >> 2;   // warp 32(M) x 64(N)

    float acc[2][8][4];
    #pragma unroll
    for (int a = 0; a < 2; a++)
        #pragma unroll
        for (int b = 0; b < 8; b++)
            #pragma unroll
            for (int c = 0; c < 4; c++) acc[a][b][c] = 0.0f;

    // per-thread cp.async chunks: A 512 chunks, B 512 chunks; 2+2 per thread
    const int q0 = tid, q1 = tid + 256;
    const int r0 = q0 >> 2, c0 = q0 & 3;
    const int r1 = q1 >> 2, c1 = q1 & 3;

    auto ld_stage = [&](int st, int k0) {
        uint32_t ab = sbase + st * STG;
        uint32_t bb = ab + ATILE_B;
        CP16(ab + r0 * ROWB + c0 * 16, g_Abf  + (size_t)(bm + r0) * K_DIM + k0 + c0 * 8);
        CP16(ab + r1 * ROWB + c1 * 16, g_Abf  + (size_t)(bm + r1) * K_DIM + k0 + c1 * 8);
        CP16(bb + r0 * ROWB + c0 * 16, g_Wtbf + (size_t)(bn + r0) * K_DIM + k0 + c0 * 8);
        CP16(bb + r1 * ROWB + c1 * 16, g_Wtbf + (size_t)(bn + r1) * K_DIM + k0 + c1 * 8);
        CP_COMMIT();
    };

    // preload 4 stages
    ld_stage(0, 0);
    ld_stage(1, 32);
    ld_stage(2, 64);
    ld_stage(3, 96);

    const int lrow = (lane & 15) * ROWB;
    const int lcol = (lane >> 4) * 16;
    const bool odd = ((wid >> 2) & 1) != 0;   // one even + one odd warp PER SMSP
    const uint32_t aoff = (wr * 32) * ROWB + lrow + lcol;
    const uint32_t boff = ATILE_B + (wc * 64) * ROWB + lrow + lcol;

    // ONE frag set (24 regs), shared by both parities / both k-steps
    uint32_t a0[4], a1[4], bq[4][4];

    auto load_ks = [&](int buf, int ks) {
        uint32_t abase = sbase + buf * STG + aoff + ks * 32;
        uint32_t bbase = sbase + buf * STG + boff + ks * 32;
        LDSM4(a0, abase);
        LDSM4(a1, abase + 16 * ROWB);
        #pragma unroll
        for (int nt = 0; nt < 4; nt++)
            LDSM4(bq[nt], bbase + nt * 16 * ROWB);
    };
    auto mma_ks = [&]() {
        #pragma unroll
        for (int nt = 0; nt < 4; nt++) {
            MMA168(acc[0][2 * nt],     a0, bq[nt][0], bq[nt][2]);
            MMA168(acc[0][2 * nt + 1], a0, bq[nt][1], bq[nt][3]);
            MMA168(acc[1][2 * nt],     a1, bq[nt][0], bq[nt][2]);
            MMA168(acc[1][2 * nt + 1], a1, bq[nt][1], bq[nt][3]);
        }
    };

    // stage 0 resident, then odd warps preload iter-0 ks0 frags
    asm volatile("cp.async.wait_group 3;" ::: "memory");
    __syncthreads();
    if (odd) load_ks(0, 0);

    int bcur = 0, bnext = 1, bpre = 4;   // it%5, (it+1)%5, (it+4)%5
    for (int it = 0; it < 32; it++) {
        // stages <= it+1 resident (2 newest commits may still be in flight)
        asm volatile("cp.async.wait_group 2;" ::: "memory");
        __syncthreads();
        if (it + 4 < 32) ld_stage(bpre, (it + 4) * 32);
        else             CP_COMMIT();   // keep group FIFO accounting valid at tail

        if (!odd) {
            load_ks(bcur, 0);
            mma_ks();
            load_ks(bcur, 1);
            mma_ks();
        } else {
            mma_ks();                    // ks0 of stage it, loaded last iteration
            load_ks(bcur, 1);
            mma_ks();
            if (it + 1 < 32) load_ks(bnext, 0);
        }

        bcur = bnext;
        if (++bnext == NSTAGE) bnext = 0;
        if (++bpre == NSTAGE) bpre = 0;
    }

    // epilogue: +bias, relu, bf16 store
    #pragma unroll
    for (int mt = 0; mt < 2; mt++) {
        int row0 = bm + wr * 32 + mt * 16 + (lane >> 2);
        #pragma unroll
        for (int nt = 0; nt < 8; nt++) {
            int col = bn + wc * 64 + nt * 8 + (lane & 3) * 2;
            float2 bb = *reinterpret_cast<const float2*>(&g_bias2[col]);
            float v0 = fmaxf(acc[mt][nt][0] + bb.x, 0.0f);
            float v1 = fmaxf(acc[mt][nt][1] + bb.y, 0.0f);
            float v2 = fmaxf(acc[mt][nt][2] + bb.x, 0.0f);
            float v3 = fmaxf(acc[mt][nt][3] + bb.y, 0.0f);
            __nv_bfloat162 p0 = __floats2bfloat162_rn(v0, v1);
            __nv_bfloat162 p1 = __floats2bfloat162_rn(v2, v3);
            *reinterpret_cast<__nv_bfloat162*>(&g_actsb[(size_t)row0 * N_DIM + col]) = p0;
            *reinterpret_cast<__nv_bfloat162*>(&g_actsb[(size_t)(row0 + 8) * N_DIM + col]) = p1;
        }
    }
}

// ---------------- screening top-96 candidates (2-round radix on bf16 bits) ----------------
#define SCREEN_SMEM (65536 + 1024 + 64)
__global__ __launch_bounds__(256) void screen_kernel() {
    extern __shared__ char sm[];
    uint16_t* row = reinterpret_cast<uint16_t*>(sm);           // 65536 B
    unsigned* hist = reinterpret_cast<unsigned*>(sm + 65536);  // 256 * 4
    __shared__ int s_b, s_krem, s_T, s_cnt;
    const int r = blockIdx.x, tid = threadIdx.x;

    const uint4* src = reinterpret_cast<const uint4*>(g_actsb + (size_t)r * N_DIM);
    uint4* drow = reinterpret_cast<uint4*>(row);
    for (int i = tid; i < N_DIM / 8; i += 256) drow[i] = src[i];
    hist[tid] = 0u;
    __syncthreads();

    // round 1: high byte (positive bf16 bits order like values)
    const uint32_t* row32 = reinterpret_cast<const uint32_t*>(row);
    for (int i = tid; i < N_DIM / 2; i += 256) {
        uint32_t w = row32[i];
        uint32_t lo = w & 0xFFFFu, hi = w >> 16;
        if (lo) atomicAdd(&hist[lo >> 8], 1u);
        if (hi) atomicAdd(&hist[hi >> 8], 1u);
    }
    __syncthreads();
    if (tid == 0) {
        unsigned cum = 0; int b = 255;
        for (; b > 0; b--) {
            unsigned c = hist[b];
            if (cum + c >= (unsigned)NCAND_TGT) break;
            cum += c;
        }
        s_b = b; s_krem = NCAND_TGT - (int)cum;
    }
    __syncthreads();
    const int b = s_b;
    hist[tid] = 0u;
    __syncthreads();

    // round 2: low byte within bin b
    for (int i = tid; i < N_DIM; i += 256) {
        unsigned u = row[i];
        if ((int)(u >> 8) == b) atomicAdd(&hist[u & 0xFFu], 1u);
    }
    __syncthreads();
    if (tid == 0) {
        int krem = s_krem;
        unsigned cum = 0; int s2 = 255;
        for (; s2 > 0; s2--) {
            unsigned c = hist[s2];
            if (cum + c >= (unsigned)krem) break;
            cum += c;
        }
        s_T = (b << 8) | s2;
        s_cnt = 0;
    }
    __syncthreads();
    const unsigned T = (unsigned)s_T;

    // compact: strictly greater first (guaranteed < NCAND_TGT), then equals up to CAP
    for (int i = tid; i < N_DIM; i += 256) {
        unsigned u = row[i];
        if (u > T) {
            int p = atomicAdd(&s_cnt, 1);
            if (p < CAP) g_cand[r * CAP + p] = i;
        }
    }
    __syncthreads();
    for (int i = tid; i < N_DIM; i += 256) {
        unsigned u = row[i];
        if (u == T && u) {
            int p = atomicAdd(&s_cnt, 1);
            if (p < CAP) g_cand[r * CAP + p] = i;
        }
    }
    __syncthreads();
    if (tid == 0) g_ncand[r] = s_cnt < CAP ? s_cnt : CAP;
}

// ---------------- exact rescore + final top-64 ----------------
__global__ __launch_bounds__(256) void rescore_kernel(const float* __restrict__ x) {
    __shared__ float sx[K_DIM];
    __shared__ unsigned long long skey[CAP];
    const int r = blockIdx.x, tid = threadIdx.x;
    const int wid = tid >> 5, lane = tid & 31;

    for (int i = tid; i < K_DIM / 4; i += 256)
        *reinterpret_cast<float4*>(&sx[i * 4]) =
            *reinterpret_cast<const float4*>(&x[(size_t)r * K_DIM + i * 4]);
    if (tid < CAP) skey[tid] = 0ull;
    __syncthreads();

    const int nc = g_ncand[r];
    for (int j = wid; j < nc; j += 8) {
        const int cand = g_cand[r * CAP + j];
        const float4* wrow = reinterpret_cast<const float4*>(&g_Wt[(size_t)cand * K_DIM]);
        const float4* xr = reinterpret_cast<const float4*>(sx);
        float s = 0.0f;
        #pragma unroll
        for (int c = lane; c < 256; c += 32) {
            float4 w = wrow[c];
            float4 v = xr[c];
            s = fmaf(w.x, v.x, s); s = fmaf(w.y, v.y, s);
            s = fmaf(w.z, v.z, s); s = fmaf(w.w, v.w, s);
        }
        #pragma unroll
        for (int o = 16; o > 0; o >>= 1) s += __shfl_xor_sync(0xFFFFFFFFu, s, o);
        if (lane == 0) {
            float v = fmaxf(s + g_bias2[cand], 0.0f);
            skey[j] = ((unsigned long long)__float_as_uint(v) << 32) |
                      (unsigned long long)(~(unsigned)cand);
        }
    }
    __syncthreads();

    // bitonic sort CAP=128 keys ascending
    for (int ksz = 2; ksz <= CAP; ksz <<= 1) {
        for (int j = ksz >> 1; j > 0; j >>= 1) {
            if (tid < CAP) {
                int ixj = tid ^ j;
                if (ixj > tid) {
                    bool up = ((tid & ksz) == 0);
                    unsigned long long A = skey[tid], B = skey[ixj];
                    if (up ? (A > B) : (A < B)) { skey[tid] = B; skey[ixj] = A; }
                }
            }
            __syncthreads();
        }
    }

    if (tid < TOPK) {
        unsigned long long k = skey[CAP - 1 - tid];   // largest first
        g_tk_val[r * TOPK + tid] = __uint_as_float((unsigned)(k >> 32));
        g_tk_idx[r * TOPK + tid] = (int)(~(unsigned)(k & 0xFFFFFFFFull));
    }
}

// ---------------- sparse matryoshka decode ----------------
__global__ __launch_bounds__(256) void decode_kernel(
    const float* __restrict__ Wdec, const float* __restrict__ b_dec,
    float* __restrict__ out)
{
    const int row = blockIdx.x;
    const int tid = threadIdx.x;

    __shared__ int   sIdx[TOPK];
    __shared__ float sVal[TOPK];
    if (tid < TOPK) {
        sIdx[tid] = g_tk_idx[row * TOPK + tid];
        sVal[tid] = g_tk_val[row * TOPK + tid];
    }
    __syncthreads();

    const int d = tid * 4;
    float4 bd = *reinterpret_cast<const float4*>(&b_dec[d]);
    float4 s1 = make_float4(0.f, 0.f, 0.f, 0.f);
    float4 s2 = s1, s3 = s1;

    #pragma unroll 8
    for (int j = 0; j < TOPK; j++) {
        int   id = sIdx[j];
        float v  = sVal[j];
        float4 w = *reinterpret_cast<const float4*>(&Wdec[(size_t)id * K_DIM + d]);
        s3.x = fmaf(v, w.x, s3.x); s3.y = fmaf(v, w.y, s3.y);
        s3.z = fmaf(v, w.z, s3.z); s3.w = fmaf(v, w.w, s3.w);
        if (id < 8192) {
            s2.x = fmaf(v, w.x, s2.x); s2.y = fmaf(v, w.y, s2.y);
            s2.z = fmaf(v, w.z, s2.z); s2.w = fmaf(v, w.w, s2.w);
        }
        if (id < 2048) {
            s1.x = fmaf(v, w.x, s1.x); s1.y = fmaf(v, w.y, s1.y);
            s1.z = fmaf(v, w.z, s1.z); s1.w = fmaf(v, w.w, s1.w);
        }
    }

    const size_t roff = (size_t)row * K_DIM + d;
    const size_t gstride = (size_t)M_DIM * K_DIM;
    *reinterpret_cast<float4*>(&out[roff]) =
        make_float4(bd.x + s1.x, bd.y + s1.y, bd.z + s1.z, bd.w + s1.w);
    *reinterpret_cast<float4*>(&out[gstride + roff]) =
        make_float4(bd.x + s2.x, bd.y + s2.y, bd.z + s2.z, bd.w + s2.w);
    *reinterpret_cast<float4*>(&out[2 * gstride + roff]) =
        make_float4(bd.x + s3.x, bd.y + s3.y, bd.z + s3.z, bd.w + s3.w);
}

// ---------------- launch ----------------
extern "C" void kernel_launch(void* const* d_in, const int* in_sizes, int n_in,
                              void* d_out, int out_size)
{
    const float* x     = (const float*)d_in[0];  // [4096,1024]
    const float* W_enc = (const float*)d_in[1];  // [1024,32768]
    const float* b_enc = (const float*)d_in[2];  // [32768]
    const float* W_dec = (const float*)d_in[3];  // [32768,1024]
    const float* b_dec = (const float*)d_in[4];  // [1024]
    float* out = (float*)d_out;                  // [3,4096,1024]

    cudaFuncSetAttribute(gemm_screen_kernel,
                         cudaFuncAttributeMaxDynamicSharedMemorySize, GEMM_SMEM);
    cudaFuncSetAttribute(screen_kernel,
                         cudaFuncAttributeMaxDynamicSharedMemorySize, SCREEN_SMEM);

    conv_x_kernel<<<(M_DIM * K_DIM) / 256, 256>>>(x);
    transpose_w_kernel<<<dim3(N_DIM / 32, K_DIM / 32), dim3(32, 32)>>>(W_enc);
    bias_fold_kernel<<<N_DIM / 256, 256>>>(W_enc, b_enc, b_dec);

    gemm_screen_kernel<<<dim3(M_DIM / 128, N_DIM / 128), 256, GEMM_SMEM>>>();

    screen_kernel<<<M_DIM, 256, SCREEN_SMEM>>>();
    rescore_kernel<<<M_DIM, 256>>>(x);
    decode_kernel<<<M_DIM, 256>>>(W_dec, b_dec, out);
}